// round 14
// baseline (speedup 1.0000x reference)
#include <cuda_runtime.h>
#include <cuda_bf16.h>
#include <cstdint>

#define BATCH   32768
#define NSITES  64
#define NBULK   62
#define NPAIR   31
#define NSETS   (NPAIR * 4)            // 124 pass-sets
#define TPB     32
#define NCTA    (BATCH / 16)           // 2048 single-warp CTAs, 16 samples each

// Fragment-linear B operands for fused site-pairs:
// set S = pair*4 + g,  g: 0=M0aM0b, 1=DaM0b, 2=M0aDb, 3=DaDb
// word index = (((S*2 + limb)*4 + j)*32 + lane)*4 + m   (limb 0=hi, 1=lo)
__device__ __align__(256) uint4 g_bfrags[(NSETS + 1) * 2 * 4 * 32];

// ---------------- helpers ----------------
__device__ __forceinline__ void mma16816(float* d, const uint32_t* a, uint32_t b0, uint32_t b1) {
    asm("mma.sync.aligned.m16n8k16.row.col.f32.bf16.bf16.f32 "
        "{%0,%1,%2,%3}, {%4,%5,%6,%7}, {%8,%9}, {%0,%1,%2,%3};"
        : "+f"(d[0]), "+f"(d[1]), "+f"(d[2]), "+f"(d[3])
        : "r"(a[0]), "r"(a[1]), "r"(a[2]), "r"(a[3]), "r"(b0), "r"(b1));
}
__device__ __forceinline__ void mma16816_z(float* d, const uint32_t* a, uint32_t b0, uint32_t b1,
                                           const float* z) {
    asm("mma.sync.aligned.m16n8k16.row.col.f32.bf16.bf16.f32 "
        "{%0,%1,%2,%3}, {%4,%5,%6,%7}, {%8,%9}, {%10,%11,%12,%13};"
        : "=f"(d[0]), "=f"(d[1]), "=f"(d[2]), "=f"(d[3])
        : "r"(a[0]), "r"(a[1]), "r"(a[2]), "r"(a[3]), "r"(b0), "r"(b1),
          "f"(z[0]), "f"(z[1]), "f"(z[2]), "f"(z[3]));
}
__device__ __forceinline__ uint32_t packbf(float lo, float hi) {
    uint32_t r;
    asm("cvt.rn.bf16x2.f32 %0, %1, %2;" : "=r"(r) : "f"(hi), "f"(lo));
    return r;
}
__device__ __forceinline__ uint32_t packbf_trunc(uint32_t u0, uint32_t u1) {
    uint32_t r;
    asm("prmt.b32 %0, %1, %2, 0x7632;" : "=r"(r) : "r"(u0), "r"(u1));
    return r;
}
__device__ __forceinline__ void split2(float x0, float x1, uint32_t& hp, uint32_t& lp) {
    uint32_t u0 = __float_as_uint(x0), u1 = __float_as_uint(x1);
    hp = packbf_trunc(u0, u1);
    float l0 = x0 - __uint_as_float(u0 & 0xFFFF0000u);
    float l1 = x1 - __uint_as_float(u1 & 0xFFFF0000u);
    lp = packbf(l0, l1);
}

// one 24-MMA pass (M=16), term-major
__device__ __forceinline__ void do_pass(float acc[4][4],
                                        const uint32_t ah[2][4],
                                        const uint32_t al[2][4],
                                        const uint4* b) {
    #pragma unroll
    for (int j = 0; j < 4; j++) mma16816(acc[j], ah[0], b[j].x, b[j].y);
    #pragma unroll
    for (int j = 0; j < 4; j++) mma16816(acc[j], ah[1], b[j].z, b[j].w);
    #pragma unroll
    for (int j = 0; j < 4; j++) mma16816(acc[j], al[0], b[j].x, b[j].y);
    #pragma unroll
    for (int j = 0; j < 4; j++) mma16816(acc[j], al[1], b[j].z, b[j].w);
    #pragma unroll
    for (int j = 0; j < 4; j++) mma16816(acc[j], ah[0], b[4+j].x, b[4+j].y);
    #pragma unroll
    for (int j = 0; j < 4; j++) mma16816(acc[j], ah[1], b[4+j].z, b[4+j].w);
}
__device__ __forceinline__ void do_pass_first(float acc[4][4],
                                              const uint32_t ah[2][4],
                                              const uint32_t al[2][4],
                                              const uint4* b, const float* z4) {
    #pragma unroll
    for (int j = 0; j < 4; j++) mma16816_z(acc[j], ah[0], b[j].x, b[j].y, z4);
    #pragma unroll
    for (int j = 0; j < 4; j++) mma16816(acc[j], ah[1], b[j].z, b[j].w);
    #pragma unroll
    for (int j = 0; j < 4; j++) mma16816(acc[j], al[0], b[j].x, b[j].y);
    #pragma unroll
    for (int j = 0; j < 4; j++) mma16816(acc[j], al[1], b[j].z, b[j].w);
    #pragma unroll
    for (int j = 0; j < 4; j++) mma16816(acc[j], ah[0], b[4+j].x, b[4+j].y);
    #pragma unroll
    for (int j = 0; j < 4; j++) mma16816(acc[j], ah[1], b[4+j].z, b[4+j].w);
}

// masked copy of A fragments (per-row c bits: c0 -> even regs, c1 -> odd regs)
__device__ __forceinline__ void mask_copy(uint32_t dh[2][4], uint32_t dl[2][4],
                                          const uint32_t sh[2][4], const uint32_t sl[2][4],
                                          uint32_t c0, uint32_t c1) {
    #pragma unroll
    for (int kt = 0; kt < 2; kt++)
        #pragma unroll
        for (int h = 0; h < 2; h++) {
            dh[kt][2*h]   = c0 ? sh[kt][2*h]   : 0u;
            dl[kt][2*h]   = c0 ? sl[kt][2*h]   : 0u;
            dh[kt][2*h+1] = c1 ? sh[kt][2*h+1] : 0u;
            dl[kt][2*h+1] = c1 ? sl[kt][2*h+1] : 0u;
        }
}

// ---------------- prep: one block per (pair,g) pass-set; SMEM-staged tiny GEMM ----------------
__global__ void prep_kernel(const float* __restrict__ bulk) {
    const int S = blockIdx.x;                        // 0..123
    const int p = S >> 2;
    const int g = S & 3;
    const int selA = g & 1, selB = g >> 1;
    const float* ba = bulk + (size_t)(2 * p)     * 2048;   // site a: [d][c][e]
    const float* bb = bulk + (size_t)(2 * p + 1) * 2048;   // site b

    __shared__ float Ma[1024];   // Ma[d*32+m]
    __shared__ float Mb[1024];   // Mb[m*32+e]
    __shared__ float G[1024];    // G[k*32+n]

    for (int i = threadIdx.x; i < 1024; i += blockDim.x) {
        int r = i >> 5, c = i & 31;
        float va = ba[(r * 2 + 0) * 32 + c];
        if (selA) va = ba[(r * 2 + 1) * 32 + c] - va;
        Ma[i] = va;
        float vb = bb[(r * 2 + 0) * 32 + c];
        if (selB) vb = bb[(r * 2 + 1) * 32 + c] - vb;
        Mb[i] = vb;
    }
    __syncthreads();

    for (int i = threadIdx.x; i < 1024; i += blockDim.x) {
        int d = i >> 5, e = i & 31;
        float s = 0.0f;
        #pragma unroll
        for (int m = 0; m < 32; m++) s += Ma[d * 32 + m] * Mb[m * 32 + e];
        G[i] = s;
    }
    __syncthreads();

    for (int idx = threadIdx.x; idx < 2048; idx += blockDim.x) {
        int m    = idx & 3;
        int lane = (idx >> 2) & 31;
        int j    = (idx >> 7) & 3;
        int limb = (idx >> 9) & 1;
        int n = 8 * j + (lane >> 2);
        int k = 8 * m + 2 * (lane & 3);
        float x0 = G[k * 32 + n];
        float x1 = G[(k + 1) * 32 + n];
        float v0, v1;
        if (limb) {
            __nv_bfloat16 h0 = __float2bfloat16(x0);
            __nv_bfloat16 h1 = __float2bfloat16(x1);
            v0 = x0 - __bfloat162float(h0);
            v1 = x1 - __bfloat162float(h1);
        } else { v0 = x0; v1 = x1; }
        ((uint32_t*)g_bfrags)[(((S * 2 + limb) * 4 + j) * 32 + lane) * 4 + m] = packbf(v0, v1);
    }
}

// ---------------- main kernel: M=16 per warp, 2048 single-warp CTAs ----------------
__global__ void __launch_bounds__(TPB)
mps_mma_kernel(const int*   __restrict__ conf,
               const float* __restrict__ left,
               const float* __restrict__ right,
               float*       __restrict__ out)
{
    __shared__ float lt_s[64];
    __shared__ float rt_s[64];
    __shared__ unsigned long long masks_s[16];

    const int lane = threadIdx.x;
    const int rowq = lane >> 2;
    const int q    = lane & 3;

    lt_s[lane] = left[lane];   lt_s[lane + 32] = left[lane + 32];
    rt_s[lane] = right[lane];  rt_s[lane + 32] = right[lane + 32];

    if (lane < 16) {
        unsigned long long mask = 0;
        const int4* cp4 = (const int4*)(conf + (size_t)(blockIdx.x * 16 + lane) * NSITES);
        #pragma unroll
        for (int i = 0; i < NSITES / 4; i++) {
            int4 v = cp4[i];
            mask |= ((unsigned long long)(v.x & 1) << (4 * i))
                  | ((unsigned long long)(v.y & 1) << (4 * i + 1))
                  | ((unsigned long long)(v.z & 1) << (4 * i + 2))
                  | ((unsigned long long)(v.w & 1) << (4 * i + 3));
        }
        masks_s[lane] = mask;
    }
    __syncwarp();

    const unsigned long long mr0 = masks_s[rowq];
    const unsigned long long mr1 = masks_s[rowq + 8];

    // ---- initial env = left[c0] as bf16 hi/lo A fragments ----
    // ah/al[kt][reg]: even reg -> row rowq (mr0), odd -> rowq+8 (mr1)
    uint32_t ah[2][4], al[2][4];
    {
        const int cA = (int)(mr0 & 1ull);
        const int cB = (int)(mr1 & 1ull);
        #pragma unroll
        for (int kt = 0; kt < 2; kt++)
            #pragma unroll
            for (int h = 0; h < 2; h++) {
                int k0 = 16 * kt + 8 * h + 2 * q;
                uint32_t hA, lA, hB, lB;
                split2(lt_s[cA * 32 + k0], lt_s[cA * 32 + k0 + 1], hA, lA);
                split2(lt_s[cB * 32 + k0], lt_s[cB * 32 + k0 + 1], hB, lB);
                ah[kt][2 * h]     = hA;  ah[kt][2 * h + 1] = hB;
                al[kt][2 * h]     = lA;  al[kt][2 * h + 1] = lB;
            }
    }

    const uint4* fb = g_bfrags + lane;

    // prologue: load set 0 into buffer 0
    uint4 bb0[8], bb1[8];
    #pragma unroll
    for (int j = 0; j < 4; j++) {
        bb0[j]     = __ldg(fb + ((0 * 2 + 0) * 4 + j) * 32);
        bb0[4 + j] = __ldg(fb + ((0 * 2 + 1) * 4 + j) * 32);
    }

    const float z4[4] = {0.0f, 0.0f, 0.0f, 0.0f};
    float acc[4][4];
    uint32_t th[2][4], tl[2][4];

    for (int p = 0; p < NPAIR; p++) {
        const uint32_t c1a = (uint32_t)((mr0 >> (2 * p + 1)) & 1ull);
        const uint32_t c1b = (uint32_t)((mr1 >> (2 * p + 1)) & 1ull);
        const uint32_t c2a = (uint32_t)((mr0 >> (2 * p + 2)) & 1ull);
        const uint32_t c2b = (uint32_t)((mr1 >> (2 * p + 2)) & 1ull);

        #pragma unroll
        for (int g = 0; g < 4; g++) {
            const int S = p * 4 + g;
            uint4* cur = (g & 1) ? bb1 : bb0;
            uint4* nxt = (g & 1) ? bb0 : bb1;
            if (S + 1 < NSETS) {
                #pragma unroll
                for (int j = 0; j < 4; j++) {
                    nxt[j]     = __ldg(fb + (((S + 1) * 2 + 0) * 4 + j) * 32);
                    nxt[4 + j] = __ldg(fb + (((S + 1) * 2 + 1) * 4 + j) * 32);
                }
            }
            if (g == 0) {
                do_pass_first(acc, ah, al, cur, z4);        // E * M0a*M0b
            } else if (g == 1) {
                mask_copy(th, tl, ah, al, c1a, c1b);
                do_pass(acc, th, tl, cur);                  // c1*E * Da*M0b
            } else if (g == 2) {
                mask_copy(th, tl, ah, al, c2a, c2b);
                do_pass(acc, th, tl, cur);                  // c2*E * M0a*Db
            } else {
                #pragma unroll
                for (int kt = 0; kt < 2; kt++)
                    #pragma unroll
                    for (int h = 0; h < 2; h++) {
                        th[kt][2*h]   = c1a ? th[kt][2*h]   : 0u;
                        tl[kt][2*h]   = c1a ? tl[kt][2*h]   : 0u;
                        th[kt][2*h+1] = c1b ? th[kt][2*h+1] : 0u;
                        tl[kt][2*h+1] = c1b ? tl[kt][2*h+1] : 0u;
                    }
                do_pass(acc, th, tl, cur);                  // c1c2*E * Da*Db
            }
        }

        // ---- split pair result (acc) -> next A fragments (D-layout == A-layout) ----
        if (p + 1 < NPAIR) {
            #pragma unroll
            for (int kt = 0; kt < 2; kt++)
                #pragma unroll
                for (int h = 0; h < 2; h++) {
                    uint32_t hA, lA, hB, lB;
                    split2(acc[2 * kt + h][0], acc[2 * kt + h][1], hA, lA);
                    split2(acc[2 * kt + h][2], acc[2 * kt + h][3], hB, lB);
                    ah[kt][2 * h]     = hA;  ah[kt][2 * h + 1] = hB;
                    al[kt][2 * h]     = lA;  al[kt][2 * h + 1] = lB;
                }
        }
    }

    // ---- final dot with right[:, c63]; reduce across the 4 lanes of each row group ----
    {
        const int cA = (int)(mr0 >> 63);
        const int cB = (int)(mr1 >> 63);
        float pa = 0.0f, pb = 0.0f;
        #pragma unroll
        for (int j = 0; j < 4; j++) {
            int n0 = 8 * j + 2 * q;
            pa += acc[j][0] * rt_s[n0 * 2 + cA] + acc[j][1] * rt_s[(n0 + 1) * 2 + cA];
            pb += acc[j][2] * rt_s[n0 * 2 + cB] + acc[j][3] * rt_s[(n0 + 1) * 2 + cB];
        }
        pa += __shfl_xor_sync(0xFFFFFFFF, pa, 1);
        pa += __shfl_xor_sync(0xFFFFFFFF, pa, 2);
        pb += __shfl_xor_sync(0xFFFFFFFF, pb, 1);
        pb += __shfl_xor_sync(0xFFFFFFFF, pb, 2);
        if (q == 0) {
            int base = blockIdx.x * 16 + rowq;
            out[base]     = pa;
            out[base + 8] = pb;
        }
    }
}

extern "C" void kernel_launch(void* const* d_in, const int* in_sizes, int n_in,
                              void* d_out, int out_size) {
    const int*   conf  = (const int*)d_in[0];
    const float* left  = (const float*)d_in[1];
    const float* bulk  = (const float*)d_in[2];
    const float* right = (const float*)d_in[3];
    float*       out   = (float*)d_out;

    prep_kernel<<<NSETS, 256>>>(bulk);
    mps_mma_kernel<<<NCTA, TPB>>>(conf, left, right, out);
}

// round 16
// speedup vs baseline: 1.1212x; 1.1212x over previous
#include <cuda_runtime.h>
#include <cstdint>

#define BATCH   32768
#define NSITES  64
#define NPAIR   31
#define NSETS   (NPAIR * 4)            // 124 pass-sets
#define TPB     32
#define NCTA    (BATCH / 16)           // 2048 single-warp CTAs, 16 samples each

// Fragment-linear int8 B operands for fused site-pairs.
// set S = pair*4 + g,  g: 0=M0aM0b, 1=DaM0b, 2=M0aDb, 3=DaDb
// uint4 at [(S*4 + j)*32 + lane] = { B1 k=4q..4q+3, B1 k=16+4q..+3, B2 klow, B2 khigh }
// (col n = 8*j + (lane>>2); bytes little-endian = ascending k)
__device__ __align__(256) uint4 g_bfrags[NSETS * 4 * 32 + 32];
__device__ float g_sbinv[NPAIR];       // per-pair dequant scale (max|G|/127)

// ---------------- IMMA helpers ----------------
__device__ __forceinline__ void imma(int* d, const uint32_t* a, uint32_t b0, uint32_t b1) {
    asm("mma.sync.aligned.m16n8k32.row.col.s32.s8.s8.s32 "
        "{%0,%1,%2,%3}, {%4,%5,%6,%7}, {%8,%9}, {%0,%1,%2,%3};"
        : "+r"(d[0]), "+r"(d[1]), "+r"(d[2]), "+r"(d[3])
        : "r"(a[0]), "r"(a[1]), "r"(a[2]), "r"(a[3]), "r"(b0), "r"(b1));
}
__device__ __forceinline__ void imma_z(int* d, const uint32_t* a, uint32_t b0, uint32_t b1) {
    int z = 0;
    asm("mma.sync.aligned.m16n8k32.row.col.s32.s8.s8.s32 "
        "{%0,%1,%2,%3}, {%4,%5,%6,%7}, {%8,%9}, {%10,%10,%10,%10};"
        : "=r"(d[0]), "=r"(d[1]), "=r"(d[2]), "=r"(d[3])
        : "r"(a[0]), "r"(a[1]), "r"(a[2]), "r"(a[3]), "r"(b0), "r"(b1), "r"(z));
}

// ---------------- prep: one block per pair; G products + 2-limb s8 fragments ----------------
__global__ void prep_kernel(const float* __restrict__ bulk) {
    const int p = blockIdx.x;
    const float* ba = bulk + (size_t)(2 * p)     * 2048;   // site a: [d][c][e]
    const float* bb = bulk + (size_t)(2 * p + 1) * 2048;   // site b

    __shared__ float Ma0[1024], Da[1024], Mb0[1024], Db[1024];
    __shared__ float G[4][1024];       // G[g][k*32+n]
    __shared__ float red[256];

    for (int i = threadIdx.x; i < 1024; i += blockDim.x) {
        int r = i >> 5, c = i & 31;
        float a0 = ba[(r * 2 + 0) * 32 + c], a1 = ba[(r * 2 + 1) * 32 + c];
        Ma0[i] = a0;  Da[i] = a1 - a0;
        float b0 = bb[(r * 2 + 0) * 32 + c], b1 = bb[(r * 2 + 1) * 32 + c];
        Mb0[i] = b0;  Db[i] = b1 - b0;
    }
    __syncthreads();

    float lmax = 0.0f;
    for (int idx = threadIdx.x; idx < 4096; idx += blockDim.x) {
        int g = idx >> 10, d = (idx >> 5) & 31, e = idx & 31;
        const float* A = (g & 1)  ? Da : Ma0;
        const float* B = (g >> 1) ? Db : Mb0;
        float s = 0.0f;
        #pragma unroll
        for (int m = 0; m < 32; m++) s += A[d * 32 + m] * B[m * 32 + e];
        G[g][d * 32 + e] = s;
        lmax = fmaxf(lmax, fabsf(s));
    }
    red[threadIdx.x] = lmax;
    __syncthreads();
    for (int o = 128; o > 0; o >>= 1) {
        if (threadIdx.x < o) red[threadIdx.x] = fmaxf(red[threadIdx.x], red[threadIdx.x + o]);
        __syncthreads();
    }
    const float gmax = fmaxf(red[0], 1e-30f);
    const float sB = 127.0f / gmax;
    if (threadIdx.x == 0) g_sbinv[p] = gmax * (1.0f / 127.0f);

    // emit 512 uint4 fragment words
    for (int idx = threadIdx.x; idx < 512; idx += blockDim.x) {
        int g = idx >> 7, j = (idx >> 5) & 3, lane = idx & 31;
        int gid = lane >> 2, q = lane & 3;
        int n = 8 * j + gid;
        uint32_t w[4] = {0u, 0u, 0u, 0u};
        #pragma unroll
        for (int i = 0; i < 4; i++) {
            #pragma unroll
            for (int half = 0; half < 2; half++) {
                int k = 16 * half + 4 * q + i;
                float v = G[g][k * 32 + n] * sB;
                int i1 = __float2int_rn(v);
                int i2 = __float2int_rn((v - (float)i1) * 256.0f);
                i2 = max(-127, min(127, i2));
                w[half]     |= ((uint32_t)(i1 & 255)) << (8 * i);
                w[2 + half] |= ((uint32_t)(i2 & 255)) << (8 * i);
            }
        }
        g_bfrags[((p * 4 + g) * 4 + j) * 32 + lane] = make_uint4(w[0], w[1], w[2], w[3]);
    }
}

// ---------------- env quantize: fp32 D-frag -> 2-limb s8 A-frag via SMEM ----------------
__device__ __forceinline__ void quantize_env(const float rv[4][4], int rowq, int q,
                                             uint32_t* q1w, uint32_t* q2w,
                                             uint32_t E1[4], uint32_t E2[4],
                                             float& se0inv, float& se1inv)
{
    float m0 = 0.0f, m1 = 0.0f;
    #pragma unroll
    for (int j = 0; j < 4; j++) {
        m0 = fmaxf(m0, fmaxf(fabsf(rv[j][0]), fabsf(rv[j][1])));
        m1 = fmaxf(m1, fmaxf(fabsf(rv[j][2]), fabsf(rv[j][3])));
    }
    m0 = fmaxf(m0, __shfl_xor_sync(0xFFFFFFFF, m0, 1));
    m0 = fmaxf(m0, __shfl_xor_sync(0xFFFFFFFF, m0, 2));
    m1 = fmaxf(m1, __shfl_xor_sync(0xFFFFFFFF, m1, 1));
    m1 = fmaxf(m1, __shfl_xor_sync(0xFFFFFFFF, m1, 2));
    m0 = fmaxf(m0, 1e-30f);  m1 = fmaxf(m1, 1e-30f);
    const float se0 = 127.0f / m0, se1 = 127.0f / m1;
    se0inv = m0 * (1.0f / 127.0f);
    se1inv = m1 * (1.0f / 127.0f);

    unsigned short* h1 = (unsigned short*)q1w;
    unsigned short* h2 = (unsigned short*)q2w;
    #pragma unroll
    for (int j = 0; j < 4; j++) {
        int off0 = (rowq * 32 + 8 * j + 2 * q) >> 1;          // row rowq, u16 index
        int off1 = ((rowq + 8) * 32 + 8 * j + 2 * q) >> 1;    // row rowq+8
        float v0 = rv[j][0] * se0, v1 = rv[j][1] * se0;
        int a0 = __float2int_rn(v0);
        int b0 = max(-127, min(127, __float2int_rn((v0 - (float)a0) * 256.0f)));
        int a1 = __float2int_rn(v1);
        int b1 = max(-127, min(127, __float2int_rn((v1 - (float)a1) * 256.0f)));
        h1[off0] = (unsigned short)((a0 & 255) | ((a1 & 255) << 8));
        h2[off0] = (unsigned short)((b0 & 255) | ((b1 & 255) << 8));
        float v2 = rv[j][2] * se1, v3 = rv[j][3] * se1;
        int a2 = __float2int_rn(v2);
        int b2 = max(-127, min(127, __float2int_rn((v2 - (float)a2) * 256.0f)));
        int a3 = __float2int_rn(v3);
        int b3 = max(-127, min(127, __float2int_rn((v3 - (float)a3) * 256.0f)));
        h1[off1] = (unsigned short)((a2 & 255) | ((a3 & 255) << 8));
        h2[off1] = (unsigned short)((b2 & 255) | ((b3 & 255) << 8));
    }
    __syncwarp();
    // A-frag loads: a0=(rowq,k=4q..), a1=(rowq+8,same), a2=(rowq,16+4q..), a3=(rowq+8,..)
    E1[0] = q1w[rowq * 8 + q];          E1[1] = q1w[(rowq + 8) * 8 + q];
    E1[2] = q1w[rowq * 8 + 4 + q];      E1[3] = q1w[(rowq + 8) * 8 + 4 + q];
    E2[0] = q2w[rowq * 8 + q];          E2[1] = q2w[(rowq + 8) * 8 + q];
    E2[2] = q2w[rowq * 8 + 4 + q];      E2[3] = q2w[(rowq + 8) * 8 + 4 + q];
    __syncwarp();
}

// ---------------- main kernel: M=16 per warp, int8 2-limb, 2048 single-warp CTAs ----------------
__global__ void __launch_bounds__(TPB)
mps_mma_kernel(const int*   __restrict__ conf,
               const float* __restrict__ left,
               const float* __restrict__ right,
               float*       __restrict__ out)
{
    __shared__ float lt_s[64];
    __shared__ float rt_s[64];
    __shared__ unsigned long long masks_s[16];
    __shared__ uint32_t q1w[128], q2w[128];   // 16 rows x 32 bytes, 2 limbs

    const int lane = threadIdx.x;
    const int rowq = lane >> 2;
    const int q    = lane & 3;

    lt_s[lane] = left[lane];   lt_s[lane + 32] = left[lane + 32];
    rt_s[lane] = right[lane];  rt_s[lane + 32] = right[lane + 32];

    if (lane < 16) {
        unsigned long long mask = 0;
        const int4* cp4 = (const int4*)(conf + (size_t)(blockIdx.x * 16 + lane) * NSITES);
        #pragma unroll
        for (int i = 0; i < NSITES / 4; i++) {
            int4 v = cp4[i];
            mask |= ((unsigned long long)(v.x & 1) << (4 * i))
                  | ((unsigned long long)(v.y & 1) << (4 * i + 1))
                  | ((unsigned long long)(v.z & 1) << (4 * i + 2))
                  | ((unsigned long long)(v.w & 1) << (4 * i + 3));
        }
        masks_s[lane] = mask;
    }
    __syncwarp();

    const unsigned long long mr0 = masks_s[rowq];
    const unsigned long long mr1 = masks_s[rowq + 8];

    // initial env in D-frag fp32 layout, then quantize
    float rv[4][4];
    {
        const int cA = (int)(mr0 & 1ull);
        const int cB = (int)(mr1 & 1ull);
        #pragma unroll
        for (int j = 0; j < 4; j++) {
            int n0 = 8 * j + 2 * q;
            rv[j][0] = lt_s[cA * 32 + n0];  rv[j][1] = lt_s[cA * 32 + n0 + 1];
            rv[j][2] = lt_s[cB * 32 + n0];  rv[j][3] = lt_s[cB * 32 + n0 + 1];
        }
    }
    uint32_t E1[4], E2[4];
    float se0inv, se1inv;
    quantize_env(rv, rowq, q, q1w, q2w, E1, E2, se0inv, se1inv);

    const uint4* fb = g_bfrags + lane;
    uint4 bb0[4], bb1[4];
    #pragma unroll
    for (int j = 0; j < 4; j++) bb0[j] = __ldg(fb + j * 32);   // set 0

    int acch[4][4], accl[4][4];
    uint32_t t1[4], t2[4];

    for (int p = 0; p < NPAIR; p++) {
        const float sbinv = g_sbinv[p];
        const uint32_t c1a = (uint32_t)((mr0 >> (2 * p + 1)) & 1ull);
        const uint32_t c1b = (uint32_t)((mr1 >> (2 * p + 1)) & 1ull);
        const uint32_t c2a = (uint32_t)((mr0 >> (2 * p + 2)) & 1ull);
        const uint32_t c2b = (uint32_t)((mr1 >> (2 * p + 2)) & 1ull);

        #pragma unroll
        for (int g = 0; g < 4; g++) {
            const int S = p * 4 + g;
            uint4* cur = (g & 1) ? bb1 : bb0;
            uint4* nxt = (g & 1) ? bb0 : bb1;
            if (S + 1 < NSETS) {
                #pragma unroll
                for (int j = 0; j < 4; j++) nxt[j] = __ldg(fb + ((S + 1) * 4 + j) * 32);
            }
            if (g == 0) {
                #pragma unroll
                for (int j = 0; j < 4; j++) {
                    imma_z(acch[j], E1, cur[j].x, cur[j].y);
                    imma_z(accl[j], E1, cur[j].z, cur[j].w);
                    imma  (accl[j], E2, cur[j].x, cur[j].y);
                }
            } else {
                if (g == 1) {
                    t1[0] = c1a ? E1[0] : 0u;  t1[1] = c1b ? E1[1] : 0u;
                    t1[2] = c1a ? E1[2] : 0u;  t1[3] = c1b ? E1[3] : 0u;
                    t2[0] = c1a ? E2[0] : 0u;  t2[1] = c1b ? E2[1] : 0u;
                    t2[2] = c1a ? E2[2] : 0u;  t2[3] = c1b ? E2[3] : 0u;
                } else if (g == 2) {
                    t1[0] = c2a ? E1[0] : 0u;  t1[1] = c2b ? E1[1] : 0u;
                    t1[2] = c2a ? E1[2] : 0u;  t1[3] = c2b ? E1[3] : 0u;
                    t2[0] = c2a ? E2[0] : 0u;  t2[1] = c2b ? E2[1] : 0u;
                    t2[2] = c2a ? E2[2] : 0u;  t2[3] = c2b ? E2[3] : 0u;
                } else {   // g == 3: mask the c2 copies again by c1 -> c1*c2
                    t1[0] = c1a ? t1[0] : 0u;  t1[1] = c1b ? t1[1] : 0u;
                    t1[2] = c1a ? t1[2] : 0u;  t1[3] = c1b ? t1[3] : 0u;
                    t2[0] = c1a ? t2[0] : 0u;  t2[1] = c1b ? t2[1] : 0u;
                    t2[2] = c1a ? t2[2] : 0u;  t2[3] = c1b ? t2[3] : 0u;
                }
                #pragma unroll
                for (int j = 0; j < 4; j++) {
                    imma(acch[j], t1, cur[j].x, cur[j].y);
                    imma(accl[j], t1, cur[j].z, cur[j].w);
                    imma(accl[j], t2, cur[j].x, cur[j].y);
                }
            }
        }

        // dequant: r = (acc_hi + acc_lo/256) * sEinv * sBinv
        const float k0 = se0inv * sbinv;
        const float k1 = se1inv * sbinv;
        #pragma unroll
        for (int j = 0; j < 4; j++) {
            rv[j][0] = ((float)acch[j][0] + (float)accl[j][0] * (1.0f / 256.0f)) * k0;
            rv[j][1] = ((float)acch[j][1] + (float)accl[j][1] * (1.0f / 256.0f)) * k0;
            rv[j][2] = ((float)acch[j][2] + (float)accl[j][2] * (1.0f / 256.0f)) * k1;
            rv[j][3] = ((float)acch[j][3] + (float)accl[j][3] * (1.0f / 256.0f)) * k1;
        }

        if (p + 1 < NPAIR)
            quantize_env(rv, rowq, q, q1w, q2w, E1, E2, se0inv, se1inv);
    }

    // ---- final dot with right[:, c63]; reduce across the 4 lanes of each row group ----
    {
        const int cA = (int)(mr0 >> 63);
        const int cB = (int)(mr1 >> 63);
        float pa = 0.0f, pb = 0.0f;
        #pragma unroll
        for (int j = 0; j < 4; j++) {
            int n0 = 8 * j + 2 * q;
            pa += rv[j][0] * rt_s[n0 * 2 + cA] + rv[j][1] * rt_s[(n0 + 1) * 2 + cA];
            pb += rv[j][2] * rt_s[n0 * 2 + cB] + rv[j][3] * rt_s[(n0 + 1) * 2 + cB];
        }
        pa += __shfl_xor_sync(0xFFFFFFFF, pa, 1);
        pa += __shfl_xor_sync(0xFFFFFFFF, pa, 2);
        pb += __shfl_xor_sync(0xFFFFFFFF, pb, 1);
        pb += __shfl_xor_sync(0xFFFFFFFF, pb, 2);
        if (q == 0) {
            int base = blockIdx.x * 16 + rowq;
            out[base]     = pa;
            out[base + 8] = pb;
        }
    }
}

extern "C" void kernel_launch(void* const* d_in, const int* in_sizes, int n_in,
                              void* d_out, int out_size) {
    const int*   conf  = (const int*)d_in[0];
    const float* left  = (const float*)d_in[1];
    const float* bulk  = (const float*)d_in[2];
    const float* right = (const float*)d_in[3];
    float*       out   = (float*)d_out;

    prep_kernel<<<NPAIR, 256>>>(bulk);
    mps_mma_kernel<<<NCTA, TPB>>>(conf, left, right, out);
}